// round 1
// baseline (speedup 1.0000x reference)
#include <cuda_runtime.h>
#include <cstdint>

// ---------------- problem constants ----------------
constexpr int kB   = 16;
constexpr int kS1  = 512;
constexpr int kS2  = 40;
constexpr int kDV  = 1024;
constexpr int kDT  = 300;
constexpr int kAD  = 256;   // attn_dim
constexpr int kNO  = 500;   // output dim
constexpr int kM   = kB * kS1;      // 8192 rows
constexpr int kCONT = 4 * kAD;      // 1024

// ---------------- scratch (no cudaMalloc allowed) ----------------
__device__ float g_f[kB * kS2 * kAD];          // (b, s2, a)  f = text@w2
__device__ float g_e[kB * kS1 * kAD];          // (b, s1, a)  e = video@w1
__device__ float g_t[kB * kS1 * kCONT];        // tanh(cont)  (8192, 1024)

// accurate-enough tanh: 1 - 2/(exp(2x)+1); err ~1e-7, saturates correctly at +-inf
__device__ __forceinline__ float tanh_fast(float x) {
    float p = __expf(2.0f * x);
    return 1.0f - __fdividef(2.0f, p + 1.0f);
}

// ---------------- kernel 1: f = text @ w2 ----------------
// one block per (b, s2) row; 256 threads, one output column each; K=300
__global__ __launch_bounds__(256) void f_kernel(const float* __restrict__ text,
                                                const float* __restrict__ w2) {
    __shared__ float st[kDT];
    const int row = blockIdx.x;                 // b*40 + s2
    const float* trow = text + row * kDT;
    for (int i = threadIdx.x; i < kDT; i += 256) st[i] = trow[i];
    __syncthreads();
    const int a = threadIdx.x;
    float acc = 0.0f;
#pragma unroll 10
    for (int k = 0; k < kDT; k++)
        acc = fmaf(st[k], w2[k * kAD + a], acc);
    g_f[row * kAD + a] = acc;
}

// ---------------- shared GEMM: C[M,NB] = A[M,K] @ Bm[K,NB] (+bias) ----------------
// BM=BN=64, BK=16, 256 threads, 4x4 microtile
template <int NB, bool HAS_BIAS>
__global__ __launch_bounds__(256) void gemm64(const float* __restrict__ A,
                                              const float* __restrict__ Bm,
                                              const float* __restrict__ bias,
                                              float* __restrict__ C,
                                              int M, int K) {
    __shared__ float As[16][68];   // [k][row], padded to 68 (16B-aligned rows, low-conflict)
    __shared__ float Bs[16][64];   // [k][col]

    const int tid = threadIdx.x;
    const int tx = tid & 15, ty = tid >> 4;
    const int row0 = blockIdx.y * 64, col0 = blockIdx.x * 64;

    const int arow = tid >> 2;          // 0..63
    const int ak   = (tid & 3) * 4;     // 0,4,8,12
    const int brow = tid >> 4;          // 0..15
    const int bcol = (tid & 15) * 4;    // 0..60
    const int gn   = col0 + bcol;
    const bool bok = (NB % 64 == 0) || (gn < NB);

    const float* Ap = A + (size_t)(row0 + arow) * K + ak;
    const float* Bp = Bm + (size_t)brow * NB + gn;

    float c[4][4];
#pragma unroll
    for (int i = 0; i < 4; i++)
#pragma unroll
        for (int j = 0; j < 4; j++) c[i][j] = 0.0f;

    for (int kt = 0; kt < K; kt += 16) {
        float4 av = *(const float4*)(Ap + kt);
        As[ak + 0][arow] = av.x;
        As[ak + 1][arow] = av.y;
        As[ak + 2][arow] = av.z;
        As[ak + 3][arow] = av.w;
        float4 bv = make_float4(0.f, 0.f, 0.f, 0.f);
        if (bok) bv = *(const float4*)(Bp + (size_t)kt * NB);
        *(float4*)&Bs[brow][bcol] = bv;
        __syncthreads();
#pragma unroll
        for (int k = 0; k < 16; k++) {
            float4 a4 = *(const float4*)&As[k][ty * 4];
            float4 b4 = *(const float4*)&Bs[k][tx * 4];
            float ar[4] = {a4.x, a4.y, a4.z, a4.w};
            float br[4] = {b4.x, b4.y, b4.z, b4.w};
#pragma unroll
            for (int i = 0; i < 4; i++)
#pragma unroll
                for (int j = 0; j < 4; j++)
                    c[i][j] = fmaf(ar[i], br[j], c[i][j]);
        }
        __syncthreads();
    }

    if (bok) {
#pragma unroll
        for (int i = 0; i < 4; i++) {
            const int gm = row0 + ty * 4 + i;
            float4 o;
            o.x = c[i][0]; o.y = c[i][1]; o.z = c[i][2]; o.w = c[i][3];
            if (HAS_BIAS) {
                o.x += bias[gn + 0]; o.y += bias[gn + 1];
                o.z += bias[gn + 2]; o.w += bias[gn + 3];
            }
            *(float4*)&C[(size_t)gm * NB + gn] = o;
        }
    }
}

// ---------------- kernel 3: fused attention core ----------------
// grid (32, 16): block handles 16 s1-rows of one batch; 256 threads (8 warps)
// smem: f tile (40x256), e rows (16x256), logits/attn (16x40), w3, bias
__global__ __launch_bounds__(256) void attn_kernel(const float* __restrict__ w3,
                                                   const float* __restrict__ bias) {
    extern __shared__ float sm[];
    float* sf   = sm;                       // 10240
    float* se   = sf + kS2 * kAD;           // 4096
    float* slog = se + 16 * kAD;            // 640
    float* sw3  = slog + 16 * kS2;          // 256
    float* sb   = sw3 + kAD;                // 256

    const int tid = threadIdx.x;
    const int b = blockIdx.y;
    const int s1base = blockIdx.x * 16;

    // --- load phase ---
    {
        const float4* fsrc = (const float4*)(g_f + (size_t)b * kS2 * kAD);
        float4* fdst = (float4*)sf;
        for (int i = tid; i < kS2 * kAD / 4; i += 256) fdst[i] = fsrc[i];
        const float4* esrc = (const float4*)(g_e + ((size_t)b * kS1 + s1base) * kAD);
        float4* edst = (float4*)se;
        for (int i = tid; i < 16 * kAD / 4; i += 256) edst[i] = esrc[i];
        sw3[tid] = w3[tid];
        sb[tid]  = bias[tid];
    }
    __syncthreads();

    const int w = tid >> 5, l = tid & 31;

    // per-lane w3 slice: a = 8l..8l+7
    float w3r[8];
    {
        float4 u = *(const float4*)&sw3[8 * l];
        float4 v = *(const float4*)&sw3[8 * l + 4];
        w3r[0] = u.x; w3r[1] = u.y; w3r[2] = u.z; w3r[3] = u.w;
        w3r[4] = v.x; w3r[5] = v.y; w3r[6] = v.z; w3r[7] = v.w;
    }
    float bb[8];
    {
        float4 u = *(const float4*)&sb[8 * l];
        float4 v = *(const float4*)&sb[8 * l + 4];
        bb[0] = u.x; bb[1] = u.y; bb[2] = u.z; bb[3] = u.w;
        bb[4] = v.x; bb[5] = v.y; bb[6] = v.z; bb[7] = v.w;
    }

    // --- logits: warp w handles rows {w, w+8}, all 40 s2 dots of length 256 ---
#pragma unroll
    for (int rr = 0; rr < 2; rr++) {
        const int r = w + rr * 8;
        float eb[8];
        {
            float4 u = *(const float4*)&se[r * kAD + 8 * l];
            float4 v = *(const float4*)&se[r * kAD + 8 * l + 4];
            eb[0] = u.x + bb[0]; eb[1] = u.y + bb[1]; eb[2] = u.z + bb[2]; eb[3] = u.w + bb[3];
            eb[4] = v.x + bb[4]; eb[5] = v.y + bb[5]; eb[6] = v.z + bb[6]; eb[7] = v.w + bb[7];
        }
        for (int s = 0; s < kS2; s++) {
            const float* fr = sf + s * kAD + 8 * l;
            float4 f0 = *(const float4*)fr;
            float4 f1 = *(const float4*)(fr + 4);
            float fv[8] = {f0.x, f0.y, f0.z, f0.w, f1.x, f1.y, f1.z, f1.w};
            float acc = 0.0f;
#pragma unroll
            for (int j = 0; j < 8; j++)
                acc = fmaf(tanh_fast(eb[j] + fv[j]), w3r[j], acc);
#pragma unroll
            for (int o = 16; o; o >>= 1)
                acc += __shfl_xor_sync(0xffffffffu, acc, o);
            if (l == 0) slog[r * kS2 + s] = acc;
        }
    }
    __syncwarp();

    // --- softmax over s2 (same warp owns its rows) ---
#pragma unroll
    for (int rr = 0; rr < 2; rr++) {
        const int r = w + rr * 8;
        float v0 = slog[r * kS2 + l];                       // s = 0..31
        float v1 = (l < 8) ? slog[r * kS2 + 32 + l]         // s = 32..39
                           : __int_as_float(0xff800000);    // -inf
        float m = fmaxf(v0, v1);
#pragma unroll
        for (int o = 16; o; o >>= 1)
            m = fmaxf(m, __shfl_xor_sync(0xffffffffu, m, o));
        float e0 = __expf(v0 - m);
        float e1 = (l < 8) ? __expf(v1 - m) : 0.0f;
        float ssum = e0 + e1;
#pragma unroll
        for (int o = 16; o; o >>= 1)
            ssum += __shfl_xor_sync(0xffffffffu, ssum, o);
        float inv = __fdividef(1.0f, ssum);
        slog[r * kS2 + l] = e0 * inv;
        if (l < 8) slog[r * kS2 + 32 + l] = e1 * inv;
    }
    __syncthreads();

    // --- text_attn + cont + tanh: thread owns column a for all 16 rows ---
    const int a = tid;
    float ta[16];
#pragma unroll
    for (int r = 0; r < 16; r++) ta[r] = 0.0f;
    for (int s = 0; s < kS2; s++) {
        float fv = sf[s * kAD + a];
#pragma unroll
        for (int r = 0; r < 16; r++)
            ta[r] = fmaf(slog[r * kS2 + s], fv, ta[r]);
    }
    float* outb = g_t + ((size_t)b * kS1 + s1base) * kCONT;
#pragma unroll
    for (int r = 0; r < 16; r++) {
        float ev = se[r * kAD + a];
        float tv = ta[r];
        float* orow = outb + (size_t)r * kCONT;
        orow[a]            = tanh_fast(ev);
        orow[kAD + a]      = tanh_fast(tv);
        orow[2 * kAD + a]  = tanh_fast(ev * tv);
        orow[3 * kAD + a]  = tanh_fast(ev - tv);
    }
}

// ---------------- launch ----------------
extern "C" void kernel_launch(void* const* d_in, const int* in_sizes, int n_in,
                              void* d_out, int out_size) {
    const float* video = (const float*)d_in[0];
    const float* text  = (const float*)d_in[1];
    const float* w1    = (const float*)d_in[2];
    const float* w2    = (const float*)d_in[3];
    const float* w3    = (const float*)d_in[4];
    const float* bias  = (const float*)d_in[5];
    const float* w4    = (const float*)d_in[6];
    const float* b4    = (const float*)d_in[7];
    float* out = (float*)d_out;

    float *pe, *pt;
    cudaGetSymbolAddress((void**)&pe, g_e);
    cudaGetSymbolAddress((void**)&pt, g_t);

    const int smem = (kS2 * kAD + 16 * kAD + 16 * kS2 + 2 * kAD) * (int)sizeof(float); // 61952
    cudaFuncSetAttribute(attn_kernel, cudaFuncAttributeMaxDynamicSharedMemorySize, smem);

    // 1) f = text @ w2
    f_kernel<<<kB * kS2, 256>>>(text, w2);
    // 2) e = video @ w1
    gemm64<kAD, false><<<dim3(kAD / 64, kM / 64), 256>>>(video, w1, nullptr, pe, kM, kDV);
    // 3) fused attention: logits -> softmax -> text_attn -> tanh(cont) into g_t
    attn_kernel<<<dim3(kS1 / 16, kB), 256, smem>>>(w3, bias);
    // 4) out = tanh(cont) @ w4 + b4
    gemm64<kNO, true><<<dim3((kNO + 63) / 64, kM / 64), 256>>>(pt, w4, b4, out, kM, kDV);
}

// round 2
// speedup vs baseline: 1.1771x; 1.1771x over previous
#include <cuda_runtime.h>
#include <cstdint>

// ---------------- problem constants ----------------
constexpr int kB   = 16;
constexpr int kS1  = 512;
constexpr int kS2  = 40;
constexpr int kDV  = 1024;
constexpr int kDT  = 300;
constexpr int kAD  = 256;   // attn_dim
constexpr int kNO  = 500;   // output dim
constexpr int kM   = kB * kS1;      // 8192 rows
constexpr int kCONT = 4 * kAD;      // 1024

// ---------------- scratch (no cudaMalloc allowed) ----------------
__device__ float g_f[kB * kS2 * kAD];          // (b, s2, a)  f = text@w2
__device__ float g_e[kB * kS1 * kAD];          // (b, s1, a)  e = video@w1
__device__ float g_t[kB * kS1 * kCONT];        // tanh(cont)  (8192, 1024)

// accurate-enough tanh: 1 - 2/(exp(2x)+1)
__device__ __forceinline__ float tanh_fast(float x) {
    float p = __expf(2.0f * x);
    return 1.0f - __fdividef(2.0f, p + 1.0f);
}

// ---------------- kernel 1: f = text @ w2 ----------------
__global__ __launch_bounds__(256) void f_kernel(const float* __restrict__ text,
                                                const float* __restrict__ w2) {
    __shared__ float st[kDT];
    const int row = blockIdx.x;                 // b*40 + s2
    const float* trow = text + row * kDT;
    for (int i = threadIdx.x; i < kDT; i += 256) st[i] = trow[i];
    __syncthreads();
    const int a = threadIdx.x;
    float acc = 0.0f;
#pragma unroll 10
    for (int k = 0; k < kDT; k++)
        acc = fmaf(st[k], w2[k * kAD + a], acc);
    g_f[row * kAD + a] = acc;
}

// ---------------- GEMM: C[M,NB] = A[M,K] @ Bm[K,NB] (+bias) ----------------
// BM=128, BN=64, BK=16; 256 threads; 8x4 microtile; double-buffered smem,
// register-prefetch pipeline, one __syncthreads per k-tile.
template <int NB, bool HAS_BIAS>
__global__ __launch_bounds__(256) void gemm128(const float* __restrict__ A,
                                               const float* __restrict__ Bm,
                                               const float* __restrict__ bias,
                                               float* __restrict__ C,
                                               int M, int K) {
    __shared__ float As[2][16][128];   // [buf][k][m]
    __shared__ float Bs[2][16][64];    // [buf][k][n]

    const int tid = threadIdx.x;
    const int tx = tid & 15;           // 0..15 -> N (4 cols each)
    const int ty = tid >> 4;           // 0..15 -> M (8 rows each)
    const int row0 = blockIdx.y * 128, col0 = blockIdx.x * 64;

    // A loader mapping: thread -> (row ar, k-offset ak), 2 float4 along K
    const int ar = tid >> 1;           // 0..127
    const int ak = (tid & 1) * 8;      // 0 or 8
    const float* Ap = A + (size_t)(row0 + ar) * K + ak;

    // B loader mapping: thread -> (k-row br, col bc), 1 float4
    const int br = tid >> 4;           // 0..15
    const int bc = (tid & 15) * 4;     // 0..60
    const int gnl = col0 + bc;
    const bool bok = (NB % 64 == 0) || (gnl < NB);
    const float* Bp = Bm + (size_t)br * NB + gnl;

    float4 pa0, pa1, pb;

    float c[8][4];
#pragma unroll
    for (int i = 0; i < 8; i++)
#pragma unroll
        for (int j = 0; j < 4; j++) c[i][j] = 0.0f;

    // prologue: fetch + stage tile 0
    pa0 = *(const float4*)(Ap + 0);
    pa1 = *(const float4*)(Ap + 4);
    pb  = bok ? *(const float4*)(Bp) : make_float4(0.f, 0.f, 0.f, 0.f);
    {
        As[0][ak + 0][ar] = pa0.x; As[0][ak + 1][ar] = pa0.y;
        As[0][ak + 2][ar] = pa0.z; As[0][ak + 3][ar] = pa0.w;
        As[0][ak + 4][ar] = pa1.x; As[0][ak + 5][ar] = pa1.y;
        As[0][ak + 6][ar] = pa1.z; As[0][ak + 7][ar] = pa1.w;
        *(float4*)&Bs[0][br][bc] = pb;
    }
    __syncthreads();

    int buf = 0;
    for (int kt = 16; kt < K; kt += 16) {
        // issue global prefetch for next tile
        pa0 = *(const float4*)(Ap + kt);
        pa1 = *(const float4*)(Ap + kt + 4);
        pb  = bok ? *(const float4*)(Bp + (size_t)kt * NB)
                  : make_float4(0.f, 0.f, 0.f, 0.f);

        // compute current tile
#pragma unroll
        for (int k = 0; k < 16; k++) {
            float4 a0 = *(const float4*)&As[buf][k][ty * 8];
            float4 a1 = *(const float4*)&As[buf][k][ty * 8 + 4];
            float4 b0 = *(const float4*)&Bs[buf][k][tx * 4];
            float av[8] = {a0.x, a0.y, a0.z, a0.w, a1.x, a1.y, a1.z, a1.w};
            float bv[4] = {b0.x, b0.y, b0.z, b0.w};
#pragma unroll
            for (int i = 0; i < 8; i++)
#pragma unroll
                for (int j = 0; j < 4; j++)
                    c[i][j] = fmaf(av[i], bv[j], c[i][j]);
        }

        // stage prefetched tile into the other buffer
        const int nb = buf ^ 1;
        As[nb][ak + 0][ar] = pa0.x; As[nb][ak + 1][ar] = pa0.y;
        As[nb][ak + 2][ar] = pa0.z; As[nb][ak + 3][ar] = pa0.w;
        As[nb][ak + 4][ar] = pa1.x; As[nb][ak + 5][ar] = pa1.y;
        As[nb][ak + 6][ar] = pa1.z; As[nb][ak + 7][ar] = pa1.w;
        *(float4*)&Bs[nb][br][bc] = pb;
        __syncthreads();
        buf = nb;
    }

    // epilogue compute on last tile
#pragma unroll
    for (int k = 0; k < 16; k++) {
        float4 a0 = *(const float4*)&As[buf][k][ty * 8];
        float4 a1 = *(const float4*)&As[buf][k][ty * 8 + 4];
        float4 b0 = *(const float4*)&Bs[buf][k][tx * 4];
        float av[8] = {a0.x, a0.y, a0.z, a0.w, a1.x, a1.y, a1.z, a1.w};
        float bv[4] = {b0.x, b0.y, b0.z, b0.w};
#pragma unroll
        for (int i = 0; i < 8; i++)
#pragma unroll
            for (int j = 0; j < 4; j++)
                c[i][j] = fmaf(av[i], bv[j], c[i][j]);
    }

    // write out: 8 rows x float4
    const int gn = col0 + tx * 4;
    if ((NB % 64 == 0) || (gn < NB)) {
        float4 badd;
        if (HAS_BIAS) badd = *(const float4*)&bias[gn];
#pragma unroll
        for (int i = 0; i < 8; i++) {
            const int gm = row0 + ty * 8 + i;
            float4 o;
            o.x = c[i][0]; o.y = c[i][1]; o.z = c[i][2]; o.w = c[i][3];
            if (HAS_BIAS) {
                o.x += badd.x; o.y += badd.y; o.z += badd.z; o.w += badd.w;
            }
            *(float4*)&C[(size_t)gm * NB + gn] = o;
        }
    }
}

// ---------------- kernel 3: fused attention core ----------------
__global__ __launch_bounds__(256) void attn_kernel(const float* __restrict__ w3,
                                                   const float* __restrict__ bias) {
    extern __shared__ float sm[];
    float* sf   = sm;                       // 40*256
    float* se   = sf + kS2 * kAD;           // 16*256
    float* slog = se + 16 * kAD;            // 16*40
    float* sw3  = slog + 16 * kS2;          // 256
    float* sb   = sw3 + kAD;                // 256

    const int tid = threadIdx.x;
    const int b = blockIdx.y;
    const int s1base = blockIdx.x * 16;

    {
        const float4* fsrc = (const float4*)(g_f + (size_t)b * kS2 * kAD);
        float4* fdst = (float4*)sf;
        for (int i = tid; i < kS2 * kAD / 4; i += 256) fdst[i] = fsrc[i];
        const float4* esrc = (const float4*)(g_e + ((size_t)b * kS1 + s1base) * kAD);
        float4* edst = (float4*)se;
        for (int i = tid; i < 16 * kAD / 4; i += 256) edst[i] = esrc[i];
        sw3[tid] = w3[tid];
        sb[tid]  = bias[tid];
    }
    __syncthreads();

    const int w = tid >> 5, l = tid & 31;

    float w3r[8];
    {
        float4 u = *(const float4*)&sw3[8 * l];
        float4 v = *(const float4*)&sw3[8 * l + 4];
        w3r[0] = u.x; w3r[1] = u.y; w3r[2] = u.z; w3r[3] = u.w;
        w3r[4] = v.x; w3r[5] = v.y; w3r[6] = v.z; w3r[7] = v.w;
    }
    float bb[8];
    {
        float4 u = *(const float4*)&sb[8 * l];
        float4 v = *(const float4*)&sb[8 * l + 4];
        bb[0] = u.x; bb[1] = u.y; bb[2] = u.z; bb[3] = u.w;
        bb[4] = v.x; bb[5] = v.y; bb[6] = v.z; bb[7] = v.w;
    }

#pragma unroll
    for (int rr = 0; rr < 2; rr++) {
        const int r = w + rr * 8;
        float eb[8];
        {
            float4 u = *(const float4*)&se[r * kAD + 8 * l];
            float4 v = *(const float4*)&se[r * kAD + 8 * l + 4];
            eb[0] = u.x + bb[0]; eb[1] = u.y + bb[1]; eb[2] = u.z + bb[2]; eb[3] = u.w + bb[3];
            eb[4] = v.x + bb[4]; eb[5] = v.y + bb[5]; eb[6] = v.z + bb[6]; eb[7] = v.w + bb[7];
        }
        for (int s = 0; s < kS2; s++) {
            const float* fr = sf + s * kAD + 8 * l;
            float4 f0 = *(const float4*)fr;
            float4 f1 = *(const float4*)(fr + 4);
            float fv[8] = {f0.x, f0.y, f0.z, f0.w, f1.x, f1.y, f1.z, f1.w};
            float acc = 0.0f;
#pragma unroll
            for (int j = 0; j < 8; j++)
                acc = fmaf(tanh_fast(eb[j] + fv[j]), w3r[j], acc);
#pragma unroll
            for (int o = 16; o; o >>= 1)
                acc += __shfl_xor_sync(0xffffffffu, acc, o);
            if (l == 0) slog[r * kS2 + s] = acc;
        }
    }
    __syncwarp();

#pragma unroll
    for (int rr = 0; rr < 2; rr++) {
        const int r = w + rr * 8;
        float v0 = slog[r * kS2 + l];
        float v1 = (l < 8) ? slog[r * kS2 + 32 + l]
                           : __int_as_float(0xff800000);
        float m = fmaxf(v0, v1);
#pragma unroll
        for (int o = 16; o; o >>= 1)
            m = fmaxf(m, __shfl_xor_sync(0xffffffffu, m, o));
        float e0 = __expf(v0 - m);
        float e1 = (l < 8) ? __expf(v1 - m) : 0.0f;
        float ssum = e0 + e1;
#pragma unroll
        for (int o = 16; o; o >>= 1)
            ssum += __shfl_xor_sync(0xffffffffu, ssum, o);
        float inv = __fdividef(1.0f, ssum);
        slog[r * kS2 + l] = e0 * inv;
        if (l < 8) slog[r * kS2 + 32 + l] = e1 * inv;
    }
    __syncthreads();

    const int a = tid;
    float ta[16];
#pragma unroll
    for (int r = 0; r < 16; r++) ta[r] = 0.0f;
    for (int s = 0; s < kS2; s++) {
        float fv = sf[s * kAD + a];
#pragma unroll
        for (int r = 0; r < 16; r++)
            ta[r] = fmaf(slog[r * kS2 + s], fv, ta[r]);
    }
    float* outb = g_t + ((size_t)b * kS1 + s1base) * kCONT;
#pragma unroll
    for (int r = 0; r < 16; r++) {
        float ev = se[r * kAD + a];
        float tv = ta[r];
        float* orow = outb + (size_t)r * kCONT;
        orow[a]            = tanh_fast(ev);
        orow[kAD + a]      = tanh_fast(tv);
        orow[2 * kAD + a]  = tanh_fast(ev * tv);
        orow[3 * kAD + a]  = tanh_fast(ev - tv);
    }
}

// ---------------- launch ----------------
extern "C" void kernel_launch(void* const* d_in, const int* in_sizes, int n_in,
                              void* d_out, int out_size) {
    const float* video = (const float*)d_in[0];
    const float* text  = (const float*)d_in[1];
    const float* w1    = (const float*)d_in[2];
    const float* w2    = (const float*)d_in[3];
    const float* w3    = (const float*)d_in[4];
    const float* bias  = (const float*)d_in[5];
    const float* w4    = (const float*)d_in[6];
    const float* b4    = (const float*)d_in[7];
    float* out = (float*)d_out;

    float *pe, *pt;
    cudaGetSymbolAddress((void**)&pe, g_e);
    cudaGetSymbolAddress((void**)&pt, g_t);

    const int smem = (kS2 * kAD + 16 * kAD + 16 * kS2 + 2 * kAD) * (int)sizeof(float); // 61952
    cudaFuncSetAttribute(attn_kernel, cudaFuncAttributeMaxDynamicSharedMemorySize, smem);

    // 1) f = text @ w2
    f_kernel<<<kB * kS2, 256>>>(text, w2);
    // 2) e = video @ w1
    gemm128<kAD, false><<<dim3(kAD / 64, kM / 128), 256>>>(video, w1, nullptr, pe, kM, kDV);
    // 3) fused attention: logits -> softmax -> text_attn -> tanh(cont) into g_t
    attn_kernel<<<dim3(kS1 / 16, kB), 256, smem>>>(w3, bias);
    // 4) out = tanh(cont) @ w4 + b4
    gemm128<kNO, true><<<dim3((kNO + 63) / 64, kM / 128), 256>>>(pt, w4, b4, out, kM, kDV);
}

// round 4
// speedup vs baseline: 1.7816x; 1.5136x over previous
#include <cuda_runtime.h>
#include <cuda_fp16.h>
#include <cstdint>

// ---------------- problem constants ----------------
constexpr int kB   = 16;
constexpr int kS1  = 512;
constexpr int kS2  = 40;
constexpr int kDV  = 1024;
constexpr int kDT  = 300;
constexpr int kAD  = 256;
constexpr int kNO  = 500;
constexpr int kM   = kB * kS1;      // 8192
constexpr int kCONT = 4 * kAD;      // 1024
constexpr int kK3 = 3 * kDV;        // 3072 (fp16-split tripled K)

// ---------------- scratch ----------------
__device__ float g_f[kB * kS2 * kAD];
__device__ float g_e[kB * kS1 * kAD];
__device__ __half g_a1[(size_t)kM * kK3];   // video split:      [Ah, Ah, Al]
__device__ __half g_a2[(size_t)kM * kK3];   // tanh(cont) split: [Ah, Ah, Al]
__device__ __half g_b1[256 * kK3];          // w1^T split:       [Bh, Bl, Bh]
__device__ __half g_b4[512 * kK3];          // w4^T split (padded 500->512)

// ---------------- asm helpers (sm_80-era, compile for base sm_103) ----------------
__device__ __forceinline__ uint32_t smem_u32(const void* p) {
    uint32_t a;
    asm("{ .reg .u64 t; cvta.to.shared.u64 t, %1; cvt.u32.u64 %0, t; }" : "=r"(a) : "l"(p));
    return a;
}
#define CP_ASYNC16(dst, src) \
    asm volatile("cp.async.cg.shared.global [%0], [%1], 16;" :: "r"(dst), "l"(src))
#define CP_COMMIT() asm volatile("cp.async.commit_group;" ::: "memory")
#define CP_WAIT1()  asm volatile("cp.async.wait_group 1;" ::: "memory")
#define LDSM4(r0, r1, r2, r3, a) \
    asm volatile("ldmatrix.sync.aligned.m8n8.x4.shared.b16 {%0,%1,%2,%3}, [%4];" \
                 : "=r"(r0), "=r"(r1), "=r"(r2), "=r"(r3) : "r"(a))
#define MMA16816(d, a, b0, b1) \
    asm volatile("mma.sync.aligned.m16n8k16.row.col.f32.f16.f16.f32 " \
                 "{%0,%1,%2,%3}, {%4,%5,%6,%7}, {%8,%9}, {%0,%1,%2,%3};" \
                 : "+f"((d)[0]), "+f"((d)[1]), "+f"((d)[2]), "+f"((d)[3]) \
                 : "r"((a)[0]), "r"((a)[1]), "r"((a)[2]), "r"((a)[3]), "r"(b0), "r"(b1))

__device__ __forceinline__ void split_h(float v, __half& h, __half& l) {
    h = __float2half_rn(v);
    l = __float2half_rn(v - __half2float(h));
}

// ---------------- kernel: video (fp32) -> g_a1 fp16 split ----------------
__global__ __launch_bounds__(256) void conv_video(const float* __restrict__ v) {
    const int id = blockIdx.x * 256 + threadIdx.x;   // kM*kDV/4 work items
    const int m = id >> 8;
    const int kq = (id & 255) << 2;
    float4 u = *(const float4*)(v + (size_t)m * kDV + kq);
    float f[4] = {u.x, u.y, u.z, u.w};
    __half h[4], l[4];
#pragma unroll
    for (int i = 0; i < 4; i++) split_h(f[i], h[i], l[i]);
    __half2 h0 = __halves2half2(h[0], h[1]), h1 = __halves2half2(h[2], h[3]);
    __half2 l0 = __halves2half2(l[0], l[1]), l1 = __halves2half2(l[2], l[3]);
    uint2 hv = {*(uint32_t*)&h0, *(uint32_t*)&h1};
    uint2 lv = {*(uint32_t*)&l0, *(uint32_t*)&l1};
    const size_t base = (size_t)m * kK3 + kq;
    *(uint2*)&g_a1[base]            = hv;
    *(uint2*)&g_a1[base + kDV]      = hv;
    *(uint2*)&g_a1[base + 2 * kDV]  = lv;
}

// ---------------- kernel: transpose + split weights ----------------
// W is [kDV][NSRC] fp32; output Bp rows n: [Bh(k), Bl(k), Bh(k)] fp16, K-contig
template <int NSRC>
__global__ __launch_bounds__(256) void prep_w(const float* __restrict__ W,
                                              __half* __restrict__ Bp) {
    __shared__ float t[64][65];
    const int k0 = blockIdx.x * 64, n0 = blockIdx.y * 64;
    const int tid = threadIdx.x;
    const int tx = tid & 63, ty = tid >> 6;
#pragma unroll
    for (int i = 0; i < 16; i++) {
        const int kk = ty + i * 4;
        const int n = n0 + tx;
        t[kk][tx] = (n < NSRC) ? W[(size_t)(k0 + kk) * NSRC + n] : 0.0f;
    }
    __syncthreads();
    const int nl = tid >> 2;
    const int kq = (tid & 3) * 16;
    __align__(16) __half hb[16], lb[16];
#pragma unroll
    for (int j = 0; j < 16; j++) split_h(t[kq + j][nl], hb[j], lb[j]);
    const size_t base = (size_t)(n0 + nl) * kK3 + k0 + kq;
    const uint4* hr = (const uint4*)hb;
    const uint4* lr = (const uint4*)lb;
    *(uint4*)&Bp[base]               = hr[0]; *(uint4*)&Bp[base + 8]               = hr[1];
    *(uint4*)&Bp[base + kDV]         = lr[0]; *(uint4*)&Bp[base + kDV + 8]         = lr[1];
    *(uint4*)&Bp[base + 2 * kDV]     = hr[0]; *(uint4*)&Bp[base + 2 * kDV + 8]     = hr[1];
}

// ---------------- kernel: f = text @ w2 (fp32, tiny) ----------------
__global__ __launch_bounds__(256) void f_kernel(const float* __restrict__ text,
                                                const float* __restrict__ w2) {
    __shared__ float st[kDT];
    const int row = blockIdx.x;
    const float* trow = text + row * kDT;
    for (int i = threadIdx.x; i < kDT; i += 256) st[i] = trow[i];
    __syncthreads();
    const int a = threadIdx.x;
    float acc = 0.0f;
#pragma unroll 10
    for (int k = 0; k < kDT; k++)
        acc = fmaf(st[k], w2[k * kAD + a], acc);
    g_f[row * kAD + a] = acc;
}

// ---------------- HMMA GEMM: C[M,NOUT] = A[M,3072] @ B[ncols][3072]^T ----------------
// Block 128x128, 8 warps (2x4), warp 64x32, BK=32, 3-stage cp.async pipeline.
// smem stage = A[128][40] + B[128][40] fp16 = 20480 B; 3 stages = 61440 B.
template <int NOUT, bool HAS_BIAS>
__global__ __launch_bounds__(256) void hgemm(const __half* __restrict__ A,
                                             const __half* __restrict__ B,
                                             const float* __restrict__ bias,
                                             float* __restrict__ C) {
    constexpr int NS = kK3 / 32;   // 96 stages
    extern __shared__ char smc[];
    const uint32_t sb = smem_u32(smc);
    const int tid = threadIdx.x, lane = tid & 31, wid = tid >> 5;
    const int row0 = blockIdx.y * 128, col0 = blockIdx.x * 128;

    // ---- loader mapping: each thread copies 2 A-chunks + 2 B-chunks of 16B ----
    const int lr = tid >> 2;            // 0..63
    const int lq = tid & 3;             // 16B chunk within 64B k-slab
    const __half* As0 = A + (size_t)(row0 + lr) * kK3 + lq * 8;
    const __half* As1 = A + (size_t)(row0 + 64 + lr) * kK3 + lq * 8;
    const __half* Bs0 = B + (size_t)(col0 + lr) * kK3 + lq * 8;
    const __half* Bs1 = B + (size_t)(col0 + 64 + lr) * kK3 + lq * 8;
    const uint32_t dA0 = sb + lr * 80 + lq * 16;
    const uint32_t dA1 = sb + (64 + lr) * 80 + lq * 16;
    const uint32_t dB0 = sb + 10240 + lr * 80 + lq * 16;
    const uint32_t dB1 = sb + 10240 + (64 + lr) * 80 + lq * 16;

    auto load_stage = [&](int st, int kt) {
        const uint32_t so = st * 20480;
        const size_t ko = (size_t)kt * 32;
        CP_ASYNC16(dA0 + so, As0 + ko);
        CP_ASYNC16(dA1 + so, As1 + ko);
        CP_ASYNC16(dB0 + so, Bs0 + ko);
        CP_ASYNC16(dB1 + so, Bs1 + ko);
    };

    // ---- compute mapping ----
    const int m_off = (wid >> 2) * 64;
    const int n_off = (wid & 3) * 32;
    const uint32_t a_lrow = (lane & 7) + ((lane >> 3) & 1) * 8;
    const uint32_t a_lk   = (lane >> 4) * 8;
    const uint32_t b_lrow = (lane & 7) + ((lane >> 4) & 1) * 8;
    const uint32_t b_lk   = ((lane >> 3) & 1) * 8;
    const uint32_t aoff = (m_off + a_lrow) * 80 + a_lk * 2;
    const uint32_t boff = 10240 + (n_off + b_lrow) * 80 + b_lk * 2;

    float acc[4][4][4];
#pragma unroll
    for (int i = 0; i < 4; i++)
#pragma unroll
        for (int j = 0; j < 4; j++)
#pragma unroll
            for (int q = 0; q < 4; q++) acc[i][j][q] = 0.0f;

    load_stage(0, 0); CP_COMMIT();
    load_stage(1, 1); CP_COMMIT();

    for (int it = 0; it < NS; it++) {
        CP_WAIT1();
        __syncthreads();
        const uint32_t stb = sb + (it % 3) * 20480;
#pragma unroll
        for (int k16 = 0; k16 < 2; k16++) {
            uint32_t a[4][4], bf[2][4];
#pragma unroll
            for (int mi = 0; mi < 4; mi++) {
                const uint32_t ad = stb + aoff + mi * 16 * 80 + k16 * 32;
                LDSM4(a[mi][0], a[mi][1], a[mi][2], a[mi][3], ad);
            }
#pragma unroll
            for (int nj = 0; nj < 2; nj++) {
                const uint32_t bd = stb + boff + nj * 16 * 80 + k16 * 32;
                LDSM4(bf[nj][0], bf[nj][1], bf[nj][2], bf[nj][3], bd);
            }
#pragma unroll
            for (int mi = 0; mi < 4; mi++)
#pragma unroll
                for (int ni = 0; ni < 4; ni++)
                    MMA16816(acc[mi][ni], a[mi],
                             bf[ni >> 1][(ni & 1) * 2], bf[ni >> 1][(ni & 1) * 2 + 1]);
        }
        if (it + 2 < NS) load_stage((it + 2) % 3, it + 2);
        CP_COMMIT();
    }

    // ---- epilogue ----
#pragma unroll
    for (int mi = 0; mi < 4; mi++) {
        const int r = row0 + m_off + mi * 16 + (lane >> 2);
#pragma unroll
        for (int ni = 0; ni < 4; ni++) {
            const int cc = col0 + n_off + ni * 8 + (lane & 3) * 2;
            if ((NOUT % 128 == 0) || (cc < NOUT)) {
                float2 o0 = {acc[mi][ni][0], acc[mi][ni][1]};
                float2 o1 = {acc[mi][ni][2], acc[mi][ni][3]};
                if (HAS_BIAS) {
                    float2 bb = *(const float2*)&bias[cc];
                    o0.x += bb.x; o0.y += bb.y;
                    o1.x += bb.x; o1.y += bb.y;
                }
                *(float2*)&C[(size_t)r * NOUT + cc] = o0;
                *(float2*)&C[(size_t)(r + 8) * NOUT + cc] = o1;
            }
        }
    }
}

// ---------------- tanh ----------------
__device__ __forceinline__ float tanh_fast(float x) {
    float p = __expf(2.0f * x);
    return 1.0f - __fdividef(2.0f, p + 1.0f);
}

// ---------------- fused attention core ----------------
__global__ __launch_bounds__(256) void attn_kernel(const float* __restrict__ w3,
                                                   const float* __restrict__ bias) {
    extern __shared__ float sm[];
    float* sf   = sm;                       // 40*256
    float* se   = sf + kS2 * kAD;           // 16*256
    float* slog = se + 16 * kAD;            // 16*40
    float* sw3  = slog + 16 * kS2;          // 256
    float* sb   = sw3 + kAD;                // 256

    const int tid = threadIdx.x;
    const int b = blockIdx.y;
    const int s1base = blockIdx.x * 16;

    {
        const float4* fsrc = (const float4*)(g_f + (size_t)b * kS2 * kAD);
        float4* fdst = (float4*)sf;
        for (int i = tid; i < kS2 * kAD / 4; i += 256) fdst[i] = fsrc[i];
        const float4* esrc = (const float4*)(g_e + ((size_t)b * kS1 + s1base) * kAD);
        float4* edst = (float4*)se;
        for (int i = tid; i < 16 * kAD / 4; i += 256) edst[i] = esrc[i];
        sw3[tid] = w3[tid];
        sb[tid]  = bias[tid];
    }
    __syncthreads();

    const int w = tid >> 5, l = tid & 31;

    float w3r[8], bb[8];
    {
        float4 u = *(const float4*)&sw3[8 * l];
        float4 v = *(const float4*)&sw3[8 * l + 4];
        w3r[0] = u.x; w3r[1] = u.y; w3r[2] = u.z; w3r[3] = u.w;
        w3r[4] = v.x; w3r[5] = v.y; w3r[6] = v.z; w3r[7] = v.w;
        float4 s = *(const float4*)&sb[8 * l];
        float4 t = *(const float4*)&sb[8 * l + 4];
        bb[0] = s.x; bb[1] = s.y; bb[2] = s.z; bb[3] = s.w;
        bb[4] = t.x; bb[5] = t.y; bb[6] = t.z; bb[7] = t.w;
    }

#pragma unroll
    for (int rr = 0; rr < 2; rr++) {
        const int r = w + rr * 8;
        float eb[8];
        {
            float4 u = *(const float4*)&se[r * kAD + 8 * l];
            float4 v = *(const float4*)&se[r * kAD + 8 * l + 4];
            eb[0] = u.x + bb[0]; eb[1] = u.y + bb[1]; eb[2] = u.z + bb[2]; eb[3] = u.w + bb[3];
            eb[4] = v.x + bb[4]; eb[5] = v.y + bb[5]; eb[6] = v.z + bb[6]; eb[7] = v.w + bb[7];
        }
        for (int s = 0; s < kS2; s++) {
            const float* fr = sf + s * kAD + 8 * l;
            float4 f0 = *(const float4*)fr;
            float4 f1 = *(const float4*)(fr + 4);
            float fv[8] = {f0.x, f0.y, f0.z, f0.w, f1.x, f1.y, f1.z, f1.w};
            float acc = 0.0f;
#pragma unroll
            for (int j = 0; j < 8; j++)
                acc = fmaf(tanh_fast(eb[j] + fv[j]), w3r[j], acc);
#pragma unroll
            for (int o = 16; o; o >>= 1)
                acc += __shfl_xor_sync(0xffffffffu, acc, o);
            if (l == 0) slog[r * kS2 + s] = acc;
        }
    }
    __syncwarp();

#pragma unroll
    for (int rr = 0; rr < 2; rr++) {
        const int r = w + rr * 8;
        float v0 = slog[r * kS2 + l];
        float v1 = (l < 8) ? slog[r * kS2 + 32 + l] : __int_as_float(0xff800000);
        float m = fmaxf(v0, v1);
#pragma unroll
        for (int o = 16; o; o >>= 1)
            m = fmaxf(m, __shfl_xor_sync(0xffffffffu, m, o));
        float e0 = __expf(v0 - m);
        float e1 = (l < 8) ? __expf(v1 - m) : 0.0f;
        float ssum = e0 + e1;
#pragma unroll
        for (int o = 16; o; o >>= 1)
            ssum += __shfl_xor_sync(0xffffffffu, ssum, o);
        float inv = __fdividef(1.0f, ssum);
        slog[r * kS2 + l] = e0 * inv;
        if (l < 8) slog[r * kS2 + 32 + l] = e1 * inv;
    }
    __syncthreads();

    const int a = tid;
    float ta[16];
#pragma unroll
    for (int r = 0; r < 16; r++) ta[r] = 0.0f;
    for (int s = 0; s < kS2; s++) {
        float fv = sf[s * kAD + a];
#pragma unroll
        for (int r = 0; r < 16; r++)
            ta[r] = fmaf(slog[r * kS2 + s], fv, ta[r]);
    }
#pragma unroll
    for (int r = 0; r < 16; r++) {
        const size_t mrow = (size_t)b * kS1 + s1base + r;
        float ev = se[r * kAD + a];
        float tv = ta[r];
        float vals[4];
        vals[0] = tanh_fast(ev);
        vals[1] = tanh_fast(tv);
        vals[2] = tanh_fast(ev * tv);
        vals[3] = tanh_fast(ev - tv);
#pragma unroll
        for (int j = 0; j < 4; j++) {
            __half h, lo;
            split_h(vals[j], h, lo);
            const size_t base2 = mrow * kK3 + j * kAD + a;
            g_a2[base2]            = h;
            g_a2[base2 + kDV]      = h;
            g_a2[base2 + 2 * kDV]  = lo;
        }
    }
}

// ---------------- launch ----------------
extern "C" void kernel_launch(void* const* d_in, const int* in_sizes, int n_in,
                              void* d_out, int out_size) {
    const float* video = (const float*)d_in[0];
    const float* text  = (const float*)d_in[1];
    const float* w1    = (const float*)d_in[2];
    const float* w2    = (const float*)d_in[3];
    const float* w3    = (const float*)d_in[4];
    const float* bias  = (const float*)d_in[5];
    const float* w4    = (const float*)d_in[6];
    const float* b4    = (const float*)d_in[7];
    float* out = (float*)d_out;

    float* pe;
    __half *pa1, *pa2, *pb1, *pb4;
    cudaGetSymbolAddress((void**)&pe,  g_e);
    cudaGetSymbolAddress((void**)&pa1, g_a1);
    cudaGetSymbolAddress((void**)&pa2, g_a2);
    cudaGetSymbolAddress((void**)&pb1, g_b1);
    cudaGetSymbolAddress((void**)&pb4, g_b4);

    const int attn_smem = (kS2 * kAD + 16 * kAD + 16 * kS2 + 2 * kAD) * (int)sizeof(float);
    cudaFuncSetAttribute(attn_kernel, cudaFuncAttributeMaxDynamicSharedMemorySize, attn_smem);
    const int gsmem = 3 * 20480;   // 61440
    cudaFuncSetAttribute(hgemm<kAD, false>, cudaFuncAttributeMaxDynamicSharedMemorySize, gsmem);
    cudaFuncSetAttribute(hgemm<kNO, true>,  cudaFuncAttributeMaxDynamicSharedMemorySize, gsmem);

    // 0) operand prep
    conv_video<<<kM * kDV / 4 / 256, 256>>>(video);
    prep_w<kAD><<<dim3(kDV / 64, 256 / 64), 256>>>(w1, pb1);
    prep_w<kNO><<<dim3(kDV / 64, 512 / 64), 256>>>(w4, pb4);
    // 1) f = text @ w2
    f_kernel<<<kB * kS2, 256>>>(text, w2);
    // 2) e = video @ w1 (HMMA, fp16-split)
    hgemm<kAD, false><<<dim3(kAD / 128, kM / 128), 256, gsmem>>>(pa1, pb1, nullptr, pe);
    // 3) fused attention -> fp16-split tanh(cont)
    attn_kernel<<<dim3(kS1 / 16, kB), 256, attn_smem>>>(w3, bias);
    // 4) out = tanh(cont) @ w4 + b4 (HMMA, fp16-split)
    hgemm<kNO, true><<<dim3(512 / 128, kM / 128), 256, gsmem>>>(pa2, pb4, b4, out);
}